// round 15
// baseline (speedup 1.0000x reference)
#include <cuda_runtime.h>
#include <cuda_bf16.h>
#include <math.h>
#include <stdint.h>

// ---------------- scratch (static device globals; no allocation) ----------------
__device__ float g_featA[32u*256*512];     // conv4 out fp32 (pre-normalize)
__device__ float g_featB[32u*256*512];
__device__ float g_corr[32u*256*256];
__device__ float g_r1[32u*10*10*128];
__device__ float g_r2[32u*6*6*64];
__device__ float g_geo[32*18];

// bf16 hi/mid/lo split buffers (each tensor split exactly once)
__device__ __nv_bfloat16 g_s1h[32u*128*128*64], g_s1m[32u*128*128*64], g_s1l[32u*128*128*64];
__device__ __nv_bfloat16 g_s2h[32u*64*64*128],  g_s2m[32u*64*64*128],  g_s2l[32u*64*64*128];
__device__ __nv_bfloat16 g_s3h[32u*32*32*256],  g_s3m[32u*32*32*256],  g_s3l[32u*32*32*256];
__device__ __nv_bfloat16 g_fAh[32u*256*512],    g_fAm[32u*256*512],    g_fAl[32u*256*512];
__device__ __nv_bfloat16 g_fBh[32u*256*512],    g_fBm[32u*256*512],    g_fBl[32u*256*512];
__device__ __nv_bfloat16 g_ch[32u*256*256],     g_cm[32u*256*256],     g_cl[32u*256*256];
__device__ __nv_bfloat16 g_wh[3153920],         g_wm[3153920],         g_wl[3153920];

// fp32 -> 3-term bf16 split, two floats packed per u32 per level.
__device__ __forceinline__ void cvt3(float a, float b,
                                     uint32_t& hi, uint32_t& mid, uint32_t& lo) {
    __nv_bfloat162 h = __floats2bfloat162_rn(a, b);
    float ra = a - __bfloat162float(__low2bfloat16(h));
    float rb = b - __bfloat162float(__high2bfloat16(h));
    __nv_bfloat162 m = __floats2bfloat162_rn(ra, rb);
    ra -= __bfloat162float(__low2bfloat16(m));
    rb -= __bfloat162float(__high2bfloat16(m));
    __nv_bfloat162 l = __floats2bfloat162_rn(ra, rb);
    hi  = reinterpret_cast<uint32_t&>(h);
    mid = reinterpret_cast<uint32_t&>(m);
    lo  = reinterpret_cast<uint32_t&>(l);
}

__device__ __forceinline__ void mma16816(float* d, const uint32_t* a, const uint32_t* b) {
    asm volatile(
        "mma.sync.aligned.m16n8k16.row.col.f32.bf16.bf16.f32 "
        "{%0,%1,%2,%3}, {%4,%5,%6,%7}, {%8,%9}, {%0,%1,%2,%3};"
        : "+f"(d[0]), "+f"(d[1]), "+f"(d[2]), "+f"(d[3])
        : "r"(a[0]), "r"(a[1]), "r"(a[2]), "r"(a[3]), "r"(b[0]), "r"(b[1]));
}
__device__ __forceinline__ void mma16816_zc(float* d, const uint32_t* a, const uint32_t* b) {
    asm volatile(
        "mma.sync.aligned.m16n8k16.row.col.f32.bf16.bf16.f32 "
        "{%0,%1,%2,%3}, {%4,%5,%6,%7}, {%8,%9}, {%10,%11,%12,%13};"
        : "=f"(d[0]), "=f"(d[1]), "=f"(d[2]), "=f"(d[3])
        : "r"(a[0]), "r"(a[1]), "r"(a[2]), "r"(a[3]), "r"(b[0]), "r"(b[1]),
          "f"(0.f), "f"(0.f), "f"(0.f), "f"(0.f));
}
__device__ __forceinline__ void ldm4(uint32_t* r, uint32_t addr) {
    asm volatile("ldmatrix.sync.aligned.m8n8.x4.shared.b16 {%0,%1,%2,%3}, [%4];"
                 : "=r"(r[0]), "=r"(r[1]), "=r"(r[2]), "=r"(r[3]) : "r"(addr));
}
__device__ __forceinline__ uint32_t smem_addr_u32(const void* p) {
    uint32_t a;
    asm("{ .reg .u64 t; cvta.to.shared.u64 t, %1; cvt.u32.u64 %0, t; }" : "=r"(a) : "l"(p));
    return a;
}
__device__ __forceinline__ void cpasync16(uint32_t dst, const void* src, int srcbytes) {
    asm volatile("cp.async.ca.shared.global [%0], [%1], 16, %2;"
                 :: "r"(dst), "l"(src), "r"(srcbytes) : "memory");
}
#define CP_COMMIT() asm volatile("cp.async.commit_group;" ::: "memory")
#define CP_WAIT1()  asm volatile("cp.async.wait_group 1;" ::: "memory")
#define CP_WAIT0()  asm volatile("cp.async.wait_group 0;" ::: "memory")

// smem layout in u32 units, BK=32: rows padded to 20 u32 (80B; 16B-aligned,
// 8 consecutive rows hit bank-groups (r*5)%8 = all 8 -> conflict-free ldmatrix)
#define A_STRIDE 20
#define SM_AHI  0
#define SM_AMID (128*20)
#define SM_ALO  (2*128*20)
#define SM_BHI  (3*128*20)
#define SM_BMID (3*128*20 + 64*20)
#define SM_BLO  (3*128*20 + 2*64*20)
#define SM_U32  (3*128*20 + 3*64*20)     // 11520 u32 = 46080 B per stage
#define SM_STAGES 2
#define SMB_TOTAL (SM_U32 * SM_STAGES * 4)   // 92160 B -> 2 CTAs/SM fit

// ====== bf16x6 tensor-core implicit-GEMM conv / GEMM ======
// BK=32, 2-stage cp.async pipeline AND 2 CTAs/SM (R14 lost the latter; this
// keeps both). Operands pre-split in gmem; per-k16 MMA windows drained into
// IEEE-RN fp32 (R11 accumulator fix). Tile M=128, N=64; 8 warps (4M x 2N).
template<int CIN,int COUT,int HIN,int WIN,int HOUT,int WOUT,int KH,int KW,int STRIDE,
         bool MGUARD,bool BKM,int NTOT,bool WRITEF32,bool WRITESPLIT,bool RELU>
__global__ __launch_bounds__(256, 2)
void conv_mma(const __nv_bfloat16* __restrict__ inh, const __nv_bfloat16* __restrict__ inm,
              const __nv_bfloat16* __restrict__ inl,
              const __nv_bfloat16* __restrict__ wth, const __nv_bfloat16* __restrict__ wtm,
              const __nv_bfloat16* __restrict__ wtl,
              float* __restrict__ outf,
              __nv_bfloat16* __restrict__ outh, __nv_bfloat16* __restrict__ outm,
              __nv_bfloat16* __restrict__ outl)
{
    constexpr int M    = HOUT * WOUT;
    constexpr int CPT  = CIN / 32;               // 32-wide k-chunks per tap
    constexpr int KCH  = KH * KW * CPT;

    extern __shared__ uint32_t smem[];
    uint32_t sb = smem_addr_u32(smem);

    int tid = threadIdx.x;
    int wid = tid >> 5, lane = tid & 31;
    int m0 = blockIdx.x * 128, n0 = blockIdx.y * 64;
    int img = blockIdx.z;

    // A producer: 2 threads per row, 16 k each (2 x 16B per level)
    int ar = tid >> 1;
    int ak0 = (tid & 1) * 16;                    // element offset
    int am = m0 + ar;
    int aoh = am / WOUT, aow = am % WOUT;
    int aoffA = ar * A_STRIDE + (ak0 >> 1);      // u32 offset within level

    // B producer: 4 threads per row, 8 k each (1 x 16B per level)
    int br = tid >> 2;
    int bk0 = (tid & 3) * 8;
    int boffB = br * A_STRIDE + (bk0 >> 1);

    // warp tiling
    int wm = wid >> 1, wn = wid & 1;
    int g = lane >> 2, t = lane & 3;

    // ldmatrix per-lane address offsets (u32 units, within a level)
    int arsel = ((lane >> 3) & 1) * 8 + (lane & 7);
    int acol  = (lane >> 4) * 4;
    int aoffs[2];
    #pragma unroll
    for (int mt = 0; mt < 2; ++mt)
        aoffs[mt] = (wm*32 + mt*16 + arsel) * A_STRIDE + acol;
    int brsel = ((lane >> 4) & 1) * 8 + (lane & 7);
    int bcol  = ((lane >> 3) & 1) * 4;
    int boffs[2];
    #pragma unroll
    for (int ntp = 0; ntp < 2; ++ntp)
        boffs[ntp] = (wn*32 + ntp*16 + brsel) * A_STRIDE + bcol;

    float acc[2][4][4];
    #pragma unroll
    for (int i = 0; i < 2; ++i)
        #pragma unroll
        for (int j = 0; j < 4; ++j)
            #pragma unroll
            for (int q = 0; q < 4; ++q) acc[i][j][q] = 0.f;

    // ---- producer: issue cp.asyncs for chunk c into stage s (9 x 16B/thread)
    auto produce = [&](int c, int s) {
        int tap  = c / CPT;
        int cin0 = (c % CPT) * 32;
        int kh = tap / KW, kw = tap - kh * KW;
        uint32_t stg = sb + (uint32_t)s * SM_U32 * 4;
        // A
        {
            int ih = aoh * STRIDE + kh, iw = aow * STRIDE + kw;
            bool ok = (ih < HIN) && (iw < WIN);
            if (MGUARD) ok = ok && (am < M);
            int sz = ok ? 16 : 0;
            size_t off = ok ? ((size_t)img * HIN * WIN * CIN
                             + ((size_t)ih * WIN + iw) * CIN + cin0 + ak0) : 0;
            uint32_t dh = stg + (SM_AHI  + aoffA) * 4;
            uint32_t dm = stg + (SM_AMID + aoffA) * 4;
            uint32_t dl = stg + (SM_ALO  + aoffA) * 4;
            const char* ph = reinterpret_cast<const char*>(inh + off);
            const char* pm = reinterpret_cast<const char*>(inm + off);
            const char* pl = reinterpret_cast<const char*>(inl + off);
            #pragma unroll
            for (int jj = 0; jj < 2; ++jj) {
                cpasync16(dh + jj*16, ph + jj*16, sz);
                cpasync16(dm + jj*16, pm + jj*16, sz);
                cpasync16(dl + jj*16, pl + jj*16, sz);
            }
        }
        // B
        {
            size_t off = BKM
                ? ((size_t)img * NTOT + n0 + br) * CIN + cin0 + bk0
                : ((size_t)tap * COUT + n0 + br) * CIN + cin0 + bk0;
            cpasync16(stg + (SM_BHI  + boffB) * 4, wth + off, 16);
            cpasync16(stg + (SM_BMID + boffB) * 4, wtm + off, 16);
            cpasync16(stg + (SM_BLO  + boffB) * 4, wtl + off, 16);
        }
    };

    produce(0, 0);
    CP_COMMIT();

    for (int c = 0; c < KCH; ++c) {
        if (c + 1 < KCH) {
            produce(c + 1, (c + 1) & 1);
            CP_COMMIT();
            CP_WAIT1();
        } else {
            CP_WAIT0();
        }
        __syncthreads();

        uint32_t stg = sb + (uint32_t)(c & 1) * SM_U32 * 4;
        uint32_t sbAhi = stg + SM_AHI*4, sbAmid = stg + SM_AMID*4, sbAlo = stg + SM_ALO*4;
        uint32_t sbBhi = stg + SM_BHI*4, sbBmid = stg + SM_BMID*4, sbBlo = stg + SM_BLO*4;

        #pragma unroll
        for (int ks = 0; ks < 2; ++ks) {
            int kp = ks * 8;
            uint32_t ah[2][4], am_[2][4], al[2][4];
            #pragma unroll
            for (int mt = 0; mt < 2; ++mt) {
                ldm4(ah[mt],  sbAhi  + (aoffs[mt] + kp) * 4);
                ldm4(am_[mt], sbAmid + (aoffs[mt] + kp) * 4);
                ldm4(al[mt],  sbAlo  + (aoffs[mt] + kp) * 4);
            }
            #pragma unroll
            for (int ntp = 0; ntp < 2; ++ntp) {
                uint32_t bh[4], bm[4], bl[4];
                ldm4(bh, sbBhi  + (boffs[ntp] + kp) * 4);
                ldm4(bm, sbBmid + (boffs[ntp] + kp) * 4);
                ldm4(bl, sbBlo  + (boffs[ntp] + kp) * 4);
                #pragma unroll
                for (int half = 0; half < 2; ++half) {
                    int nt = ntp * 2 + half;
                    const uint32_t* pbh = bh + half*2;
                    const uint32_t* pbm = bm + half*2;
                    const uint32_t* pbl = bl + half*2;
                    #pragma unroll
                    for (int mt = 0; mt < 2; ++mt) {
                        float tmp[4];
                        mma16816_zc(tmp, ah[mt],  pbh);
                        mma16816(tmp, ah[mt],  pbm);
                        mma16816(tmp, am_[mt], pbh);
                        mma16816(tmp, ah[mt],  pbl);
                        mma16816(tmp, am_[mt], pbm);
                        mma16816(tmp, al[mt],  pbh);
                        acc[mt][nt][0] += tmp[0];
                        acc[mt][nt][1] += tmp[1];
                        acc[mt][nt][2] += tmp[2];
                        acc[mt][nt][3] += tmp[3];
                    }
                }
            }
        }
        __syncthreads();
    }

    // ---- epilogue
    #pragma unroll
    for (int mt = 0; mt < 2; ++mt) {
        #pragma unroll
        for (int half = 0; half < 2; ++half) {
            int row = m0 + wm * 32 + mt * 16 + g + half * 8;
            if (MGUARD && row >= M) continue;
            size_t base = ((size_t)img * M + row) * COUT + n0 + wn * 32;
            #pragma unroll
            for (int nt = 0; nt < 4; ++nt) {
                float x0 = acc[mt][nt][half*2 + 0];
                float x1 = acc[mt][nt][half*2 + 1];
                if (RELU) { x0 = fmaxf(x0, 0.f); x1 = fmaxf(x1, 0.f); }
                size_t idx = base + nt*8 + 2*t;
                if (WRITEF32)
                    *reinterpret_cast<float2*>(outf + idx) = make_float2(x0, x1);
                if (WRITESPLIT) {
                    uint32_t h, m, l;
                    cvt3(x0, x1, h, m, l);
                    *reinterpret_cast<uint32_t*>(outh + idx) = h;
                    *reinterpret_cast<uint32_t*>(outm + idx) = m;
                    *reinterpret_cast<uint32_t*>(outl + idx) = l;
                }
            }
        }
    }
}

// ---------------- weight transpose + split: (tap,cin,cout)->(tap,cout,cin) ----
__global__ void split_w(const float* __restrict__ in,
                        __nv_bfloat16* __restrict__ oh, __nv_bfloat16* __restrict__ om,
                        __nv_bfloat16* __restrict__ ol,
                        int cin, int cout, int total)
{
    int idx = blockIdx.x * 256 + threadIdx.x;
    if (idx >= total) return;
    int n = idx % cout;
    int rest = idx / cout;
    int ci = rest % cin;
    int tap = rest / cin;
    float w = in[idx];
    __nv_bfloat16 h = __float2bfloat16(w);
    float r = w - __bfloat162float(h);
    __nv_bfloat16 m = __float2bfloat16(r);
    r -= __bfloat162float(m);
    __nv_bfloat16 l = __float2bfloat16(r);
    size_t o = ((size_t)tap * cout + n) * cin + ci;
    oh[o] = h; om[o] = m; ol[o] = l;
}

// ---------------- conv1: 256x256x3 -> 128x128x64 split, stride 2, pad_lo=0 ----
__global__ void conv1_kernel(const float* __restrict__ in, const float* __restrict__ w,
                             __nv_bfloat16* __restrict__ oh, __nv_bfloat16* __restrict__ om,
                             __nv_bfloat16* __restrict__ ol)
{
    int idx = blockIdx.x * 256 + threadIdx.x;   // handles output elems 2*idx, 2*idx+1
    int e = idx * 2;
    int oc = e & 63;                             // even
    int p  = e >> 6;
    int ow = p & 127; p >>= 7;
    int ohh = p & 127; p >>= 7;
    int b  = p;
    float a0 = 0.f, a1 = 0.f;
    #pragma unroll
    for (int kh = 0; kh < 3; ++kh) {
        int ih = ohh * 2 + kh;
        if (ih >= 256) continue;
        #pragma unroll
        for (int kw = 0; kw < 3; ++kw) {
            int iw = ow * 2 + kw;
            if (iw >= 256) continue;
            const float* ip = in + ((size_t)(b * 256 + ih) * 256 + iw) * 3;
            const float* wp = w + ((kh * 3 + kw) * 3) * 64 + oc;
            a0 += ip[0] * wp[0] + ip[1] * wp[64]  + ip[2] * wp[128];
            a1 += ip[0] * wp[1] + ip[1] * wp[65]  + ip[2] * wp[129];
        }
    }
    a0 = fmaxf(a0, 0.f);
    a1 = fmaxf(a1, 0.f);
    uint32_t h, m, l;
    cvt3(a0, a1, h, m, l);
    *reinterpret_cast<uint32_t*>(oh + e) = h;
    *reinterpret_cast<uint32_t*>(om + e) = m;
    *reinterpret_cast<uint32_t*>(ol + e) = l;
}

// ---------------- L2-normalize 512ch fp32 -> bf16x3 split ----------------------
__global__ void normalize_split(const float* __restrict__ feat,
                                __nv_bfloat16* __restrict__ oh, __nv_bfloat16* __restrict__ om,
                                __nv_bfloat16* __restrict__ ol)
{
    size_t row = blockIdx.x;
    const float* p = feat + row * 512;
    int tid = threadIdx.x;   // 128
    float4 v = *reinterpret_cast<const float4*>(p + tid * 4);
    float s = v.x*v.x + v.y*v.y + v.z*v.z + v.w*v.w;
    for (int o = 16; o > 0; o >>= 1) s += __shfl_down_sync(0xffffffffu, s, o);
    __shared__ float sw[4];
    __shared__ float sscale;
    if ((tid & 31) == 0) sw[tid >> 5] = s;
    __syncthreads();
    if (tid == 0) sscale = 1.f / (sqrtf(sw[0] + sw[1] + sw[2] + sw[3]) + 1e-6f);
    __syncthreads();
    float sc = sscale;
    v.x *= sc; v.y *= sc; v.z *= sc; v.w *= sc;
    uint32_t h0, m0, l0, h1, m1, l1;
    cvt3(v.x, v.y, h0, m0, l0);
    cvt3(v.z, v.w, h1, m1, l1);
    size_t base = row * 512 + tid * 4;
    *reinterpret_cast<uint32_t*>(oh + base)     = h0;
    *reinterpret_cast<uint32_t*>(oh + base + 2) = h1;
    *reinterpret_cast<uint32_t*>(om + base)     = m0;
    *reinterpret_cast<uint32_t*>(om + base + 2) = m1;
    *reinterpret_cast<uint32_t*>(ol + base)     = l0;
    *reinterpret_cast<uint32_t*>(ol + base + 2) = l1;
}

// ---------------- legacy FFMA igemm (small r2 conv only) ----------------------
template<int CIN,int COUT,int HIN,int WIN,int HOUT,int WOUT,int KH,int KW,int STRIDE,bool MGUARD>
__global__ __launch_bounds__(256)
void conv_igemm(const float* __restrict__ in, const float* __restrict__ wt,
                float* __restrict__ out)
{
    constexpr int M   = HOUT * WOUT;
    constexpr int CPT = CIN / 64;
    constexpr int KCH = KH * KW * CPT;
    __shared__ __align__(16) float As[64][68];
    __shared__ __align__(16) float Bs[64][68];

    int tid = threadIdx.x;
    int m0 = blockIdx.x * 64, n0 = blockIdx.y * 64;
    int img = blockIdx.z;
    const float* inb = in + (size_t)img * HIN * WIN * CIN;

    int lr = tid >> 2;
    int lc = (tid & 3) << 4;
    int m  = m0 + lr;
    int oh = m / WOUT, ow = m % WOUT;
    int ty = tid >> 4, tx = tid & 15;

    float acc[4][4] = {};
    for (int c = 0; c < KCH; ++c) {
        int tap  = c / CPT;
        int cin0 = (c % CPT) * 64;
        int kh = tap / KW, kw = tap - kh * KW;
        int ih = oh * STRIDE + kh, iw = ow * STRIDE + kw;
        bool ok = (ih < HIN) && (iw < WIN);
        if (MGUARD) ok = ok && (m < M);
        const float* ap = inb + ((size_t)ih * WIN + iw) * CIN + cin0 + lc;
        #pragma unroll
        for (int t = 0; t < 4; ++t) {
            float4 v = ok ? *reinterpret_cast<const float4*>(ap + 4 * t)
                          : make_float4(0.f, 0.f, 0.f, 0.f);
            As[lc + 4*t + 0][lr] = v.x; As[lc + 4*t + 1][lr] = v.y;
            As[lc + 4*t + 2][lr] = v.z; As[lc + 4*t + 3][lr] = v.w;
        }
        const float* bp = wt + ((size_t)tap * CIN + cin0 + lr) * COUT + n0 + lc;
        #pragma unroll
        for (int t = 0; t < 4; ++t)
            *reinterpret_cast<float4*>(&Bs[lr][lc + 4*t]) =
                *reinterpret_cast<const float4*>(bp + 4 * t);
        __syncthreads();
        #pragma unroll
        for (int kk = 0; kk < 64; ++kk) {
            float4 av = *reinterpret_cast<const float4*>(&As[kk][ty * 4]);
            float4 bv = *reinterpret_cast<const float4*>(&Bs[kk][tx * 4]);
            float ar[4] = {av.x, av.y, av.z, av.w};
            float br[4] = {bv.x, bv.y, bv.z, bv.w};
            #pragma unroll
            for (int i = 0; i < 4; ++i)
                #pragma unroll
                for (int j = 0; j < 4; ++j)
                    acc[i][j] += ar[i] * br[j];
        }
        __syncthreads();
    }
    #pragma unroll
    for (int i = 0; i < 4; ++i) {
        int mm = m0 + ty * 4 + i;
        if (MGUARD && mm >= M) continue;
        float4 v = make_float4(fmaxf(acc[i][0], 0.f), fmaxf(acc[i][1], 0.f),
                               fmaxf(acc[i][2], 0.f), fmaxf(acc[i][3], 0.f));
        *reinterpret_cast<float4*>(out + ((size_t)img * M + mm) * COUT + n0 + tx * 4) = v;
    }
}

// ---------------- dense: geo = r2_flat(2304) @ Wd(2304,18) + bd ---------------
__global__ void dense_kernel(const float* __restrict__ x, const float* __restrict__ Wd,
                             const float* __restrict__ bd, float* __restrict__ geo)
{
    int b = blockIdx.x;
    int o = threadIdx.x >> 5;
    int lane = threadIdx.x & 31;
    const float* xb = x + b * 2304;
    float acc = 0.f;
    for (int t = lane; t < 2304; t += 32)
        acc += xb[t] * Wd[t * 18 + o];
    for (int s = 16; s > 0; s >>= 1) acc += __shfl_down_sync(0xffffffffu, acc, s);
    if (lane == 0) geo[b * 18 + o] = acc + bd[o];
}

// ---------------- TPS fit + masked sum ----------------------------------------
__global__ void tps_sum_kernel(const float* __restrict__ geo, const float* __restrict__ corr,
                               float* __restrict__ out)
{
    int b = blockIdx.x, tid = threadIdx.x;
    __shared__ float sdx[9], sdy[9], swx[9], swy[9], sax[3], say[3];
    __shared__ float red[256];

    if (tid == 0) {
        const float srcx[9] = {0.f, 0.5f, 1.f, 0.f, 0.5f, 1.f, 0.f, 5.f, 1.f};
        const float srcy[9] = {0.f, 0.f,  0.f, 0.5f,0.5f, 0.5f,1.f, 1.f, 1.f};
        float dx9[9], dy9[9], vx[9], vy[9];
        for (int c = 0; c < 9; ++c) {
            float mx_ = geo[b * 18 + 2 * c], my_ = geo[b * 18 + 2 * c + 1];
            dx9[c] = srcx[c] + mx_;  dy9[c] = srcy[c] + my_;
            vx[c] = -mx_;            vy[c] = -my_;
        }
        float Mx[12][14];
        for (int i = 0; i < 12; ++i)
            for (int j = 0; j < 14; ++j) Mx[i][j] = 0.f;
        for (int i = 0; i < 9; ++i) {
            for (int j = 0; j < 9; ++j) {
                float ddx = dx9[i] - dx9[j], ddy = dy9[i] - dy9[j];
                float r = sqrtf(ddx * ddx + ddy * ddy + 1e-12f);
                Mx[i][j] = r * r * logf(r + 1e-6f);
            }
            Mx[i][9] = 1.f; Mx[i][10] = dx9[i]; Mx[i][11] = dy9[i];
            Mx[9][i] = 1.f; Mx[10][i] = dx9[i]; Mx[11][i] = dy9[i];
            Mx[i][12] = vx[i]; Mx[i][13] = vy[i];
        }
        for (int k = 0; k < 12; ++k) {
            int piv = k; float best = fabsf(Mx[k][k]);
            for (int i = k + 1; i < 12; ++i) {
                float a = fabsf(Mx[i][k]);
                if (a > best) { best = a; piv = i; }
            }
            if (piv != k)
                for (int j = k; j < 14; ++j) {
                    float t = Mx[k][j]; Mx[k][j] = Mx[piv][j]; Mx[piv][j] = t;
                }
            for (int i = k + 1; i < 12; ++i) {
                float f = Mx[i][k] / Mx[k][k];
                for (int j = k + 1; j < 14; ++j) Mx[i][j] -= f * Mx[k][j];
                Mx[i][k] = 0.f;
            }
        }
        float thx[12], thy[12];
        for (int k = 11; k >= 0; --k) {
            float sx = Mx[k][12], sy = Mx[k][13];
            for (int j = k + 1; j < 12; ++j) { sx -= Mx[k][j] * thx[j]; sy -= Mx[k][j] * thy[j]; }
            thx[k] = sx / Mx[k][k];  thy[k] = sy / Mx[k][k];
        }
        float s8x = 0.f, s8y = 0.f;
        for (int c = 1; c < 9; ++c) { s8x += thx[c]; s8y += thy[c]; }
        swx[0] = -s8x; swy[0] = -s8y;
        for (int c = 1; c < 9; ++c) { swx[c] = thx[c]; swy[c] = thy[c]; }
        sax[0] = thx[9]; sax[1] = thx[10]; sax[2] = thx[11];
        say[0] = thy[9]; say[1] = thy[10]; say[2] = thy[11];
        for (int c = 0; c < 9; ++c) { sdx[c] = dx9[c]; sdy[c] = dy9[c]; }
    }
    __syncthreads();

    int r = tid >> 4, c = tid & 15;
    float px = c * (1.f / 15.f), py = r * (1.f / 15.f);
    float zx = 0.f, zy = 0.f;
    #pragma unroll
    for (int q = 0; q < 9; ++q) {
        float ddx = px - sdx[q], ddy = py - sdy[q];
        float rr = sqrtf(ddx * ddx + ddy * ddy + 1e-12f);
        float u = rr * rr * logf(rr + 1e-6f);
        zx += u * swx[q]; zy += u * swy[q];
    }
    zx += sax[0] + px * sax[1] + py * sax[2];
    zy += say[0] + px * say[1] + py * say[2];
    float axv = (px + zx) * 15.f;
    float ayv = (py + zy) * 15.f;

    const float* col = corr + (size_t)b * 65536 + tid;
    float s = 0.f;
    for (int i = 0; i < 16; ++i) {
        if (fabsf((float)i - ayv) > 1.f) continue;
        const float* rp = col + i * 4096;
        for (int j = 0; j < 16; ++j)
            if (fabsf((float)j - axv) <= 1.f) s += rp[j * 256];
    }
    red[tid] = s;
    __syncthreads();
    for (int o = 128; o > 0; o >>= 1) {
        if (tid < o) red[tid] += red[tid + o];
        __syncthreads();
    }
    if (tid == 0) out[b] = red[0];
}

// ---------------- launch ------------------------------------------------------
extern "C" void kernel_launch(void* const* d_in, const int* in_sizes, int n_in,
                              void* d_out, int out_size)
{
    const float* imgA = (const float*)d_in[0];
    const float* imgB = (const float*)d_in[1];
    const float* W1   = (const float*)d_in[2];
    const float* W2   = (const float*)d_in[3];
    const float* W3   = (const float*)d_in[4];
    const float* W4   = (const float*)d_in[5];
    const float* Wr1  = (const float*)d_in[6];
    const float* Wr2  = (const float*)d_in[7];
    const float* Wd   = (const float*)d_in[8];
    const float* bd   = (const float*)d_in[9];
    float* out = (float*)d_out;

    float *featA, *featB, *corr, *r1, *r2, *geo;
    cudaGetSymbolAddress((void**)&featA, g_featA);
    cudaGetSymbolAddress((void**)&featB, g_featB);
    cudaGetSymbolAddress((void**)&corr,  g_corr);
    cudaGetSymbolAddress((void**)&r1,    g_r1);
    cudaGetSymbolAddress((void**)&r2,    g_r2);
    cudaGetSymbolAddress((void**)&geo,   g_geo);

    __nv_bfloat16 *s1h,*s1m,*s1l,*s2h,*s2m,*s2l,*s3h,*s3m,*s3l;
    __nv_bfloat16 *fAh,*fAm,*fAl,*fBh,*fBm,*fBl,*ch,*cm,*cl,*wh,*wm,*wl;
    cudaGetSymbolAddress((void**)&s1h, g_s1h); cudaGetSymbolAddress((void**)&s1m, g_s1m);
    cudaGetSymbolAddress((void**)&s1l, g_s1l);
    cudaGetSymbolAddress((void**)&s2h, g_s2h); cudaGetSymbolAddress((void**)&s2m, g_s2m);
    cudaGetSymbolAddress((void**)&s2l, g_s2l);
    cudaGetSymbolAddress((void**)&s3h, g_s3h); cudaGetSymbolAddress((void**)&s3m, g_s3m);
    cudaGetSymbolAddress((void**)&s3l, g_s3l);
    cudaGetSymbolAddress((void**)&fAh, g_fAh); cudaGetSymbolAddress((void**)&fAm, g_fAm);
    cudaGetSymbolAddress((void**)&fAl, g_fAl);
    cudaGetSymbolAddress((void**)&fBh, g_fBh); cudaGetSymbolAddress((void**)&fBm, g_fBm);
    cudaGetSymbolAddress((void**)&fBl, g_fBl);
    cudaGetSymbolAddress((void**)&ch, g_ch); cudaGetSymbolAddress((void**)&cm, g_cm);
    cudaGetSymbolAddress((void**)&cl, g_cl);
    cudaGetSymbolAddress((void**)&wh, g_wh); cudaGetSymbolAddress((void**)&wm, g_wm);
    cudaGetSymbolAddress((void**)&wl, g_wl);

    // transposed+split weight regions (element offsets)
    const size_t O_W2 = 0, O_W3 = 73728, O_W4 = 368640, O_Wr1 = 1548288;
    split_w<<<(73728 + 255)/256, 256>>>(W2,  wh + O_W2,  wm + O_W2,  wl + O_W2,  64, 128, 73728);
    split_w<<<(294912 + 255)/256, 256>>>(W3, wh + O_W3,  wm + O_W3,  wl + O_W3,  128, 256, 294912);
    split_w<<<(1179648 + 255)/256, 256>>>(W4, wh + O_W4, wm + O_W4, wl + O_W4, 256, 512, 1179648);
    split_w<<<(1605632 + 255)/256, 256>>>(Wr1, wh + O_Wr1, wm + O_Wr1, wl + O_Wr1, 256, 128, 1605632);

    auto mm2 = conv_mma<64, 128, 128, 128, 64, 64, 3, 3, 2, false, false, 0, false, true, true>;
    auto mm3 = conv_mma<128, 256, 64, 64, 32, 32, 3, 3, 2, false, false, 0, false, true, true>;
    auto mm4 = conv_mma<256, 512, 32, 32, 16, 16, 3, 3, 2, false, false, 0, true, false, true>;
    auto mmc = conv_mma<512, 256, 16, 16, 16, 16, 1, 1, 1, false, true, 256, true, true, false>;
    auto mr1 = conv_mma<256, 128, 16, 16, 10, 10, 7, 7, 1, true, false, 0, true, false, true>;
    cudaFuncSetAttribute(mm2, cudaFuncAttributeMaxDynamicSharedMemorySize, SMB_TOTAL);
    cudaFuncSetAttribute(mm3, cudaFuncAttributeMaxDynamicSharedMemorySize, SMB_TOTAL);
    cudaFuncSetAttribute(mm4, cudaFuncAttributeMaxDynamicSharedMemorySize, SMB_TOTAL);
    cudaFuncSetAttribute(mmc, cudaFuncAttributeMaxDynamicSharedMemorySize, SMB_TOTAL);
    cudaFuncSetAttribute(mr1, cudaFuncAttributeMaxDynamicSharedMemorySize, SMB_TOTAL);

    for (int im = 0; im < 2; ++im) {
        const float* img = im ? imgB : imgA;
        float* feat = im ? featB : featA;
        __nv_bfloat16 *fh = im ? fBh : fAh, *fm = im ? fBm : fAm, *fl = im ? fBl : fAl;
        conv1_kernel<<<65536, 256>>>(img, W1, s1h, s1m, s1l);
        mm2<<<dim3(32, 2, 32), 256, SMB_TOTAL>>>(s1h, s1m, s1l, wh + O_W2, wm + O_W2, wl + O_W2,
                                                 nullptr, s2h, s2m, s2l);
        mm3<<<dim3(8, 4, 32), 256, SMB_TOTAL>>>(s2h, s2m, s2l, wh + O_W3, wm + O_W3, wl + O_W3,
                                                nullptr, s3h, s3m, s3l);
        mm4<<<dim3(2, 8, 32), 256, SMB_TOTAL>>>(s3h, s3m, s3l, wh + O_W4, wm + O_W4, wl + O_W4,
                                                feat, nullptr, nullptr, nullptr);
        normalize_split<<<8192, 128>>>(feat, fh, fm, fl);
    }

    mmc<<<dim3(2, 4, 32), 256, SMB_TOTAL>>>(fAh, fAm, fAl, fBh, fBm, fBl, corr, ch, cm, cl);

    mr1<<<dim3(1, 2, 32), 256, SMB_TOTAL>>>(ch, cm, cl, wh + O_Wr1, wm + O_Wr1, wl + O_Wr1,
                                            r1, nullptr, nullptr, nullptr);
    conv_igemm<128, 64, 10, 10, 6, 6, 5, 5, 1, true>
        <<<dim3(1, 1, 32), 256>>>(r1, Wr2, r2);

    dense_kernel<<<32, 576>>>(r2, Wd, bd, geo);
    tps_sum_kernel<<<32, 256>>>(geo, corr, out);
}

// round 16
// speedup vs baseline: 1.1778x; 1.1778x over previous
#include <cuda_runtime.h>
#include <cuda_bf16.h>
#include <math.h>
#include <stdint.h>

// ---------------- scratch (static device globals; no allocation) ----------------
__device__ float g_featA[32u*256*512];     // conv4 out fp32 (pre-normalize)
__device__ float g_featB[32u*256*512];
__device__ float g_corr[32u*256*256];
__device__ float g_r1[32u*10*10*128];
__device__ float g_r1p[4u*32*100*128];     // split-K partials for r1
__device__ float g_r2[32u*6*6*64];
__device__ float g_geo[32*18];

// bf16 hi/mid/lo split buffers (each tensor split exactly once)
__device__ __nv_bfloat16 g_s1h[32u*128*128*64], g_s1m[32u*128*128*64], g_s1l[32u*128*128*64];
__device__ __nv_bfloat16 g_s2h[32u*64*64*128],  g_s2m[32u*64*64*128],  g_s2l[32u*64*64*128];
__device__ __nv_bfloat16 g_s3h[32u*32*32*256],  g_s3m[32u*32*32*256],  g_s3l[32u*32*32*256];
__device__ __nv_bfloat16 g_fAh[32u*256*512],    g_fAm[32u*256*512],    g_fAl[32u*256*512];
__device__ __nv_bfloat16 g_fBh[32u*256*512],    g_fBm[32u*256*512],    g_fBl[32u*256*512];
__device__ __nv_bfloat16 g_ch[32u*256*256],     g_cm[32u*256*256],     g_cl[32u*256*256];
__device__ __nv_bfloat16 g_wh[3153920],         g_wm[3153920],         g_wl[3153920];

// fp32 -> 3-term bf16 split, two floats packed per u32 per level.
__device__ __forceinline__ void cvt3(float a, float b,
                                     uint32_t& hi, uint32_t& mid, uint32_t& lo) {
    __nv_bfloat162 h = __floats2bfloat162_rn(a, b);
    float ra = a - __bfloat162float(__low2bfloat16(h));
    float rb = b - __bfloat162float(__high2bfloat16(h));
    __nv_bfloat162 m = __floats2bfloat162_rn(ra, rb);
    ra -= __bfloat162float(__low2bfloat16(m));
    rb -= __bfloat162float(__high2bfloat16(m));
    __nv_bfloat162 l = __floats2bfloat162_rn(ra, rb);
    hi  = reinterpret_cast<uint32_t&>(h);
    mid = reinterpret_cast<uint32_t&>(m);
    lo  = reinterpret_cast<uint32_t&>(l);
}

__device__ __forceinline__ void mma16816(float* d, const uint32_t* a, const uint32_t* b) {
    asm volatile(
        "mma.sync.aligned.m16n8k16.row.col.f32.bf16.bf16.f32 "
        "{%0,%1,%2,%3}, {%4,%5,%6,%7}, {%8,%9}, {%0,%1,%2,%3};"
        : "+f"(d[0]), "+f"(d[1]), "+f"(d[2]), "+f"(d[3])
        : "r"(a[0]), "r"(a[1]), "r"(a[2]), "r"(a[3]), "r"(b[0]), "r"(b[1]));
}
__device__ __forceinline__ void mma16816_zc(float* d, const uint32_t* a, const uint32_t* b) {
    asm volatile(
        "mma.sync.aligned.m16n8k16.row.col.f32.bf16.bf16.f32 "
        "{%0,%1,%2,%3}, {%4,%5,%6,%7}, {%8,%9}, {%10,%11,%12,%13};"
        : "=f"(d[0]), "=f"(d[1]), "=f"(d[2]), "=f"(d[3])
        : "r"(a[0]), "r"(a[1]), "r"(a[2]), "r"(a[3]), "r"(b[0]), "r"(b[1]),
          "f"(0.f), "f"(0.f), "f"(0.f), "f"(0.f));
}
__device__ __forceinline__ void ldm4(uint32_t* r, uint32_t addr) {
    asm volatile("ldmatrix.sync.aligned.m8n8.x4.shared.b16 {%0,%1,%2,%3}, [%4];"
                 : "=r"(r[0]), "=r"(r[1]), "=r"(r[2]), "=r"(r[3]) : "r"(addr));
}
__device__ __forceinline__ uint32_t smem_addr_u32(const void* p) {
    uint32_t a;
    asm("{ .reg .u64 t; cvta.to.shared.u64 t, %1; cvt.u32.u64 %0, t; }" : "=r"(a) : "l"(p));
    return a;
}

// smem layout in u32 units: rows padded to 36 u32 (144B: 16B-aligned rows for
// ldmatrix; 8 consecutive rows cover all 8 16B bank-groups -> conflict-free)
#define A_STRIDE 36
#define SM_AHI  0
#define SM_AMID (128*36)
#define SM_ALO  (2*128*36)
#define SM_BHI  (3*128*36)
#define SM_BMID (3*128*36 + 64*36)
#define SM_BLO  (3*128*36 + 2*64*36)
#define SM_U32  (3*128*36 + 3*64*36)     // 20736 u32 = 82944 bytes

// ====== bf16x6 tensor-core implicit-GEMM conv / GEMM (R13 design + split-K) ====
// Synchronous producers (LDG+STS.128), 2 CTAs/SM; ldmatrix fragments; per-k16
// MMA windows drained into IEEE-RN fp32 (R11 accumulator fix).
// SPLITK>1: blockIdx.y = nblk*SPLITK + sk; each sk covers KCH/SPLITK k-chunks
// and writes raw partials at (((sk*32)+img)*M + row)*COUT (RELU deferred).
template<int CIN,int COUT,int HIN,int WIN,int HOUT,int WOUT,int KH,int KW,int STRIDE,
         bool MGUARD,bool BKM,int NTOT,int SPLITK,bool WRITEF32,bool WRITESPLIT,bool RELU>
__global__ __launch_bounds__(256, 2)
void conv_mma(const __nv_bfloat16* __restrict__ inh, const __nv_bfloat16* __restrict__ inm,
              const __nv_bfloat16* __restrict__ inl,
              const __nv_bfloat16* __restrict__ wth, const __nv_bfloat16* __restrict__ wtm,
              const __nv_bfloat16* __restrict__ wtl,
              float* __restrict__ outf,
              __nv_bfloat16* __restrict__ outh, __nv_bfloat16* __restrict__ outm,
              __nv_bfloat16* __restrict__ outl)
{
    constexpr int M   = HOUT * WOUT;
    constexpr int CPT = CIN / 64;
    constexpr int KCH = KH * KW * CPT;
    constexpr int KPS = KCH / SPLITK;

    extern __shared__ uint32_t smem[];
    uint32_t* Ahi  = smem + SM_AHI;
    uint32_t* Amid = smem + SM_AMID;
    uint32_t* Alo  = smem + SM_ALO;
    uint32_t* Bhi  = smem + SM_BHI;
    uint32_t* Bmid = smem + SM_BMID;
    uint32_t* Blo  = smem + SM_BLO;
    uint32_t sb = smem_addr_u32(smem);
    uint32_t sbAhi = sb + SM_AHI*4,  sbAmid = sb + SM_AMID*4, sbAlo = sb + SM_ALO*4;
    uint32_t sbBhi = sb + SM_BHI*4,  sbBmid = sb + SM_BMID*4, sbBlo = sb + SM_BLO*4;

    int tid = threadIdx.x;
    int wid = tid >> 5, lane = tid & 31;
    int sk = 0, nblk = blockIdx.y;
    if (SPLITK > 1) { sk = blockIdx.y % SPLITK; nblk = blockIdx.y / SPLITK; }
    int m0 = blockIdx.x * 128, n0 = nblk * 64;
    int img = blockIdx.z;

    // A producer: 2 threads per row, 32 k each
    int ar = tid >> 1;
    int ak0 = (tid & 1) * 32;
    int am = m0 + ar;
    int aoh = am / WOUT, aow = am % WOUT;

    // B producer: 4 threads per row, 16 k each
    int br = tid >> 2;
    int bk0 = (tid & 3) * 16;

    // warp tiling
    int wm = wid >> 1, wn = wid & 1;
    int g = lane >> 2, t = lane & 3;

    // ldmatrix per-lane address offsets (u32 units)
    int arsel = ((lane >> 3) & 1) * 8 + (lane & 7);
    int acol  = (lane >> 4) * 4;
    int aoffs[2];
    #pragma unroll
    for (int mt = 0; mt < 2; ++mt)
        aoffs[mt] = (wm*32 + mt*16 + arsel) * A_STRIDE + acol;
    int brsel = ((lane >> 4) & 1) * 8 + (lane & 7);
    int bcol  = ((lane >> 3) & 1) * 4;
    int boffs[2];
    #pragma unroll
    for (int ntp = 0; ntp < 2; ++ntp)
        boffs[ntp] = (wn*32 + ntp*16 + brsel) * A_STRIDE + bcol;

    float acc[2][4][4];
    #pragma unroll
    for (int i = 0; i < 2; ++i)
        #pragma unroll
        for (int j = 0; j < 4; ++j)
            #pragma unroll
            for (int q = 0; q < 4; ++q) acc[i][j][q] = 0.f;

    int c0 = sk * KPS, c1 = c0 + KPS;
    for (int c = c0; c < c1; ++c) {
        int tap  = c / CPT;
        int cin0 = (c % CPT) * 64;
        int kh = tap / KW, kw = tap - kh * KW;

        // ---- A: 128 x 64 bf16x3 pre-split, pure uint4 copy
        {
            int ih = aoh * STRIDE + kh, iw = aow * STRIDE + kw;
            bool ok = (ih < HIN) && (iw < WIN);
            if (MGUARD) ok = ok && (am < M);
            size_t off = (size_t)img * HIN * WIN * CIN + ((size_t)ih * WIN + iw) * CIN
                       + cin0 + ak0;
            const uint4* ph = reinterpret_cast<const uint4*>(inh + off);
            const uint4* pm = reinterpret_cast<const uint4*>(inm + off);
            const uint4* pl = reinterpret_cast<const uint4*>(inl + off);
            uint4 z = make_uint4(0u,0u,0u,0u);
            #pragma unroll
            for (int jj = 0; jj < 4; ++jj) {
                uint4 vh = ok ? ph[jj] : z;
                uint4 vm = ok ? pm[jj] : z;
                uint4 vl = ok ? pl[jj] : z;
                int p = (ak0 >> 1) + jj*4;
                *reinterpret_cast<uint4*>(&Ahi [ar*A_STRIDE + p]) = vh;
                *reinterpret_cast<uint4*>(&Amid[ar*A_STRIDE + p]) = vm;
                *reinterpret_cast<uint4*>(&Alo [ar*A_STRIDE + p]) = vl;
            }
        }
        // ---- B: 64(n) x 64(k), pre-split k-major source
        {
            size_t off = BKM
                ? ((size_t)img * NTOT + n0 + br) * CIN + cin0 + bk0
                : ((size_t)tap * COUT + n0 + br) * CIN + cin0 + bk0;
            const uint4* ph = reinterpret_cast<const uint4*>(wth + off);
            const uint4* pm = reinterpret_cast<const uint4*>(wtm + off);
            const uint4* pl = reinterpret_cast<const uint4*>(wtl + off);
            #pragma unroll
            for (int jj = 0; jj < 2; ++jj) {
                int p = (bk0 >> 1) + jj*4;
                *reinterpret_cast<uint4*>(&Bhi [br*A_STRIDE + p]) = ph[jj];
                *reinterpret_cast<uint4*>(&Bmid[br*A_STRIDE + p]) = pm[jj];
                *reinterpret_cast<uint4*>(&Blo [br*A_STRIDE + p]) = pl[jj];
            }
        }
        __syncthreads();

        // ---- compute: 4 k16 steps; fresh MMA window per step, FADD drain
        #pragma unroll
        for (int ks = 0; ks < 4; ++ks) {
            int kp = ks * 8;
            uint32_t ah[2][4], am_[2][4], al[2][4];
            #pragma unroll
            for (int mt = 0; mt < 2; ++mt) {
                ldm4(ah[mt],  sbAhi  + (aoffs[mt] + kp) * 4);
                ldm4(am_[mt], sbAmid + (aoffs[mt] + kp) * 4);
                ldm4(al[mt],  sbAlo  + (aoffs[mt] + kp) * 4);
            }
            #pragma unroll
            for (int ntp = 0; ntp < 2; ++ntp) {
                uint32_t bh[4], bm[4], bl[4];
                ldm4(bh, sbBhi  + (boffs[ntp] + kp) * 4);
                ldm4(bm, sbBmid + (boffs[ntp] + kp) * 4);
                ldm4(bl, sbBlo  + (boffs[ntp] + kp) * 4);
                #pragma unroll
                for (int half = 0; half < 2; ++half) {
                    int nt = ntp * 2 + half;
                    const uint32_t* pbh = bh + half*2;
                    const uint32_t* pbm = bm + half*2;
                    const uint32_t* pbl = bl + half*2;
                    #pragma unroll
                    for (int mt = 0; mt < 2; ++mt) {
                        float tmp[4];
                        mma16816_zc(tmp, ah[mt],  pbh);
                        mma16816(tmp, ah[mt],  pbm);
                        mma16816(tmp, am_[mt], pbh);
                        mma16816(tmp, ah[mt],  pbl);
                        mma16816(tmp, am_[mt], pbm);
                        mma16816(tmp, al[mt],  pbh);
                        acc[mt][nt][0] += tmp[0];
                        acc[mt][nt][1] += tmp[1];
                        acc[mt][nt][2] += tmp[2];
                        acc[mt][nt][3] += tmp[3];
                    }
                }
            }
        }
        __syncthreads();
    }

    // ---- epilogue
    #pragma unroll
    for (int mt = 0; mt < 2; ++mt) {
        #pragma unroll
        for (int half = 0; half < 2; ++half) {
            int row = m0 + wm * 32 + mt * 16 + g + half * 8;
            if (MGUARD && row >= M) continue;
            size_t base = (((size_t)sk * 32 + img) * M + row) * COUT + n0 + wn * 32;
            #pragma unroll
            for (int nt = 0; nt < 4; ++nt) {
                float x0 = acc[mt][nt][half*2 + 0];
                float x1 = acc[mt][nt][half*2 + 1];
                if (RELU) { x0 = fmaxf(x0, 0.f); x1 = fmaxf(x1, 0.f); }
                size_t idx = base + nt*8 + 2*t;
                if (WRITEF32)
                    *reinterpret_cast<float2*>(outf + idx) = make_float2(x0, x1);
                if (WRITESPLIT) {
                    uint32_t h, m, l;
                    cvt3(x0, x1, h, m, l);
                    *reinterpret_cast<uint32_t*>(outh + idx) = h;
                    *reinterpret_cast<uint32_t*>(outm + idx) = m;
                    *reinterpret_cast<uint32_t*>(outl + idx) = l;
                }
            }
        }
    }
}

// ---------------- split-K reduce for r1: sum 4 partials + ReLU ----------------
__global__ void reduce_r1(const float* __restrict__ part, float* __restrict__ out)
{
    int idx = blockIdx.x * 256 + threadIdx.x;
    if (idx >= 32 * 100 * 128) return;
    const int S = 32 * 100 * 128;
    float s = part[idx] + part[S + idx] + part[2*S + idx] + part[3*S + idx];
    out[idx] = fmaxf(s, 0.f);
}

// ---------------- weight transpose + split: (tap,cin,cout)->(tap,cout,cin) ----
__global__ void split_w(const float* __restrict__ in,
                        __nv_bfloat16* __restrict__ oh, __nv_bfloat16* __restrict__ om,
                        __nv_bfloat16* __restrict__ ol,
                        int cin, int cout, int total)
{
    int idx = blockIdx.x * 256 + threadIdx.x;
    if (idx >= total) return;
    int n = idx % cout;
    int rest = idx / cout;
    int ci = rest % cin;
    int tap = rest / cin;
    float w = in[idx];
    __nv_bfloat16 h = __float2bfloat16(w);
    float r = w - __bfloat162float(h);
    __nv_bfloat16 m = __float2bfloat16(r);
    r -= __bfloat162float(m);
    __nv_bfloat16 l = __float2bfloat16(r);
    size_t o = ((size_t)tap * cout + n) * cin + ci;
    oh[o] = h; om[o] = m; ol[o] = l;
}

// ---------------- conv1: 256x256x3 -> 128x128x64 split, stride 2, pad_lo=0 ----
__global__ void conv1_kernel(const float* __restrict__ in, const float* __restrict__ w,
                             __nv_bfloat16* __restrict__ oh, __nv_bfloat16* __restrict__ om,
                             __nv_bfloat16* __restrict__ ol)
{
    int idx = blockIdx.x * 256 + threadIdx.x;   // handles output elems 2*idx, 2*idx+1
    int e = idx * 2;
    int oc = e & 63;                             // even
    int p  = e >> 6;
    int ow = p & 127; p >>= 7;
    int ohh = p & 127; p >>= 7;
    int b  = p;
    float a0 = 0.f, a1 = 0.f;
    #pragma unroll
    for (int kh = 0; kh < 3; ++kh) {
        int ih = ohh * 2 + kh;
        if (ih >= 256) continue;
        #pragma unroll
        for (int kw = 0; kw < 3; ++kw) {
            int iw = ow * 2 + kw;
            if (iw >= 256) continue;
            const float* ip = in + ((size_t)(b * 256 + ih) * 256 + iw) * 3;
            const float* wp = w + ((kh * 3 + kw) * 3) * 64 + oc;
            a0 += ip[0] * wp[0] + ip[1] * wp[64]  + ip[2] * wp[128];
            a1 += ip[0] * wp[1] + ip[1] * wp[65]  + ip[2] * wp[129];
        }
    }
    a0 = fmaxf(a0, 0.f);
    a1 = fmaxf(a1, 0.f);
    uint32_t h, m, l;
    cvt3(a0, a1, h, m, l);
    *reinterpret_cast<uint32_t*>(oh + e) = h;
    *reinterpret_cast<uint32_t*>(om + e) = m;
    *reinterpret_cast<uint32_t*>(ol + e) = l;
}

// ---------------- L2-normalize 512ch fp32 -> bf16x3 split ----------------------
__global__ void normalize_split(const float* __restrict__ feat,
                                __nv_bfloat16* __restrict__ oh, __nv_bfloat16* __restrict__ om,
                                __nv_bfloat16* __restrict__ ol)
{
    size_t row = blockIdx.x;
    const float* p = feat + row * 512;
    int tid = threadIdx.x;   // 128
    float4 v = *reinterpret_cast<const float4*>(p + tid * 4);
    float s = v.x*v.x + v.y*v.y + v.z*v.z + v.w*v.w;
    for (int o = 16; o > 0; o >>= 1) s += __shfl_down_sync(0xffffffffu, s, o);
    __shared__ float sw[4];
    __shared__ float sscale;
    if ((tid & 31) == 0) sw[tid >> 5] = s;
    __syncthreads();
    if (tid == 0) sscale = 1.f / (sqrtf(sw[0] + sw[1] + sw[2] + sw[3]) + 1e-6f);
    __syncthreads();
    float sc = sscale;
    v.x *= sc; v.y *= sc; v.z *= sc; v.w *= sc;
    uint32_t h0, m0, l0, h1, m1, l1;
    cvt3(v.x, v.y, h0, m0, l0);
    cvt3(v.z, v.w, h1, m1, l1);
    size_t base = row * 512 + tid * 4;
    *reinterpret_cast<uint32_t*>(oh + base)     = h0;
    *reinterpret_cast<uint32_t*>(oh + base + 2) = h1;
    *reinterpret_cast<uint32_t*>(om + base)     = m0;
    *reinterpret_cast<uint32_t*>(om + base + 2) = m1;
    *reinterpret_cast<uint32_t*>(ol + base)     = l0;
    *reinterpret_cast<uint32_t*>(ol + base + 2) = l1;
}

// ---------------- legacy FFMA igemm (small r2 conv only) ----------------------
template<int CIN,int COUT,int HIN,int WIN,int HOUT,int WOUT,int KH,int KW,int STRIDE,bool MGUARD>
__global__ __launch_bounds__(256)
void conv_igemm(const float* __restrict__ in, const float* __restrict__ wt,
                float* __restrict__ out)
{
    constexpr int M   = HOUT * WOUT;
    constexpr int CPT = CIN / 64;
    constexpr int KCH = KH * KW * CPT;
    __shared__ __align__(16) float As[64][68];
    __shared__ __align__(16) float Bs[64][68];

    int tid = threadIdx.x;
    int m0 = blockIdx.x * 64, n0 = blockIdx.y * 64;
    int img = blockIdx.z;
    const float* inb = in + (size_t)img * HIN * WIN * CIN;

    int lr = tid >> 2;
    int lc = (tid & 3) << 4;
    int m  = m0 + lr;
    int oh = m / WOUT, ow = m % WOUT;
    int ty = tid >> 4, tx = tid & 15;

    float acc[4][4] = {};
    for (int c = 0; c < KCH; ++c) {
        int tap  = c / CPT;
        int cin0 = (c % CPT) * 64;
        int kh = tap / KW, kw = tap - kh * KW;
        int ih = oh * STRIDE + kh, iw = ow * STRIDE + kw;
        bool ok = (ih < HIN) && (iw < WIN);
        if (MGUARD) ok = ok && (m < M);
        const float* ap = inb + ((size_t)ih * WIN + iw) * CIN + cin0 + lc;
        #pragma unroll
        for (int t = 0; t < 4; ++t) {
            float4 v = ok ? *reinterpret_cast<const float4*>(ap + 4 * t)
                          : make_float4(0.f, 0.f, 0.f, 0.f);
            As[lc + 4*t + 0][lr] = v.x; As[lc + 4*t + 1][lr] = v.y;
            As[lc + 4*t + 2][lr] = v.z; As[lc + 4*t + 3][lr] = v.w;
        }
        const float* bp = wt + ((size_t)tap * CIN + cin0 + lr) * COUT + n0 + lc;
        #pragma unroll
        for (int t = 0; t < 4; ++t)
            *reinterpret_cast<float4*>(&Bs[lr][lc + 4*t]) =
                *reinterpret_cast<const float4*>(bp + 4 * t);
        __syncthreads();
        #pragma unroll
        for (int kk = 0; kk < 64; ++kk) {
            float4 av = *reinterpret_cast<const float4*>(&As[kk][ty * 4]);
            float4 bv = *reinterpret_cast<const float4*>(&Bs[kk][tx * 4]);
            float ar[4] = {av.x, av.y, av.z, av.w};
            float br[4] = {bv.x, bv.y, bv.z, bv.w};
            #pragma unroll
            for (int i = 0; i < 4; ++i)
                #pragma unroll
                for (int j = 0; j < 4; ++j)
                    acc[i][j] += ar[i] * br[j];
        }
        __syncthreads();
    }
    #pragma unroll
    for (int i = 0; i < 4; ++i) {
        int mm = m0 + ty * 4 + i;
        if (MGUARD && mm >= M) continue;
        float4 v = make_float4(fmaxf(acc[i][0], 0.f), fmaxf(acc[i][1], 0.f),
                               fmaxf(acc[i][2], 0.f), fmaxf(acc[i][3], 0.f));
        *reinterpret_cast<float4*>(out + ((size_t)img * M + mm) * COUT + n0 + tx * 4) = v;
    }
}

// ---------------- dense: geo = r2_flat(2304) @ Wd(2304,18) + bd ---------------
__global__ void dense_kernel(const float* __restrict__ x, const float* __restrict__ Wd,
                             const float* __restrict__ bd, float* __restrict__ geo)
{
    int b = blockIdx.x;
    int o = threadIdx.x >> 5;
    int lane = threadIdx.x & 31;
    const float* xb = x + b * 2304;
    float acc = 0.f;
    for (int t = lane; t < 2304; t += 32)
        acc += xb[t] * Wd[t * 18 + o];
    for (int s = 16; s > 0; s >>= 1) acc += __shfl_down_sync(0xffffffffu, acc, s);
    if (lane == 0) geo[b * 18 + o] = acc + bd[o];
}

// ---------------- TPS fit + masked sum ----------------------------------------
__global__ void tps_sum_kernel(const float* __restrict__ geo, const float* __restrict__ corr,
                               float* __restrict__ out)
{
    int b = blockIdx.x, tid = threadIdx.x;
    __shared__ float sdx[9], sdy[9], swx[9], swy[9], sax[3], say[3];
    __shared__ float red[256];

    if (tid == 0) {
        const float srcx[9] = {0.f, 0.5f, 1.f, 0.f, 0.5f, 1.f, 0.f, 5.f, 1.f};
        const float srcy[9] = {0.f, 0.f,  0.f, 0.5f,0.5f, 0.5f,1.f, 1.f, 1.f};
        float dx9[9], dy9[9], vx[9], vy[9];
        for (int c = 0; c < 9; ++c) {
            float mx_ = geo[b * 18 + 2 * c], my_ = geo[b * 18 + 2 * c + 1];
            dx9[c] = srcx[c] + mx_;  dy9[c] = srcy[c] + my_;
            vx[c] = -mx_;            vy[c] = -my_;
        }
        float Mx[12][14];
        for (int i = 0; i < 12; ++i)
            for (int j = 0; j < 14; ++j) Mx[i][j] = 0.f;
        for (int i = 0; i < 9; ++i) {
            for (int j = 0; j < 9; ++j) {
                float ddx = dx9[i] - dx9[j], ddy = dy9[i] - dy9[j];
                float r = sqrtf(ddx * ddx + ddy * ddy + 1e-12f);
                Mx[i][j] = r * r * logf(r + 1e-6f);
            }
            Mx[i][9] = 1.f; Mx[i][10] = dx9[i]; Mx[i][11] = dy9[i];
            Mx[9][i] = 1.f; Mx[10][i] = dx9[i]; Mx[11][i] = dy9[i];
            Mx[i][12] = vx[i]; Mx[i][13] = vy[i];
        }
        for (int k = 0; k < 12; ++k) {
            int piv = k; float best = fabsf(Mx[k][k]);
            for (int i = k + 1; i < 12; ++i) {
                float a = fabsf(Mx[i][k]);
                if (a > best) { best = a; piv = i; }
            }
            if (piv != k)
                for (int j = k; j < 14; ++j) {
                    float t = Mx[k][j]; Mx[k][j] = Mx[piv][j]; Mx[piv][j] = t;
                }
            for (int i = k + 1; i < 12; ++i) {
                float f = Mx[i][k] / Mx[k][k];
                for (int j = k + 1; j < 14; ++j) Mx[i][j] -= f * Mx[k][j];
                Mx[i][k] = 0.f;
            }
        }
        float thx[12], thy[12];
        for (int k = 11; k >= 0; --k) {
            float sx = Mx[k][12], sy = Mx[k][13];
            for (int j = k + 1; j < 12; ++j) { sx -= Mx[k][j] * thx[j]; sy -= Mx[k][j] * thy[j]; }
            thx[k] = sx / Mx[k][k];  thy[k] = sy / Mx[k][k];
        }
        float s8x = 0.f, s8y = 0.f;
        for (int c = 1; c < 9; ++c) { s8x += thx[c]; s8y += thy[c]; }
        swx[0] = -s8x; swy[0] = -s8y;
        for (int c = 1; c < 9; ++c) { swx[c] = thx[c]; swy[c] = thy[c]; }
        sax[0] = thx[9]; sax[1] = thx[10]; sax[2] = thx[11];
        say[0] = thy[9]; say[1] = thy[10]; say[2] = thy[11];
        for (int c = 0; c < 9; ++c) { sdx[c] = dx9[c]; sdy[c] = dy9[c]; }
    }
    __syncthreads();

    int r = tid >> 4, c = tid & 15;
    float px = c * (1.f / 15.f), py = r * (1.f / 15.f);
    float zx = 0.f, zy = 0.f;
    #pragma unroll
    for (int q = 0; q < 9; ++q) {
        float ddx = px - sdx[q], ddy = py - sdy[q];
        float rr = sqrtf(ddx * ddx + ddy * ddy + 1e-12f);
        float u = rr * rr * logf(rr + 1e-6f);
        zx += u * swx[q]; zy += u * swy[q];
    }
    zx += sax[0] + px * sax[1] + py * sax[2];
    zy += say[0] + px * say[1] + py * say[2];
    float axv = (px + zx) * 15.f;
    float ayv = (py + zy) * 15.f;

    const float* col = corr + (size_t)b * 65536 + tid;
    float s = 0.f;
    for (int i = 0; i < 16; ++i) {
        if (fabsf((float)i - ayv) > 1.f) continue;
        const float* rp = col + i * 4096;
        for (int j = 0; j < 16; ++j)
            if (fabsf((float)j - axv) <= 1.f) s += rp[j * 256];
    }
    red[tid] = s;
    __syncthreads();
    for (int o = 128; o > 0; o >>= 1) {
        if (tid < o) red[tid] += red[tid + o];
        __syncthreads();
    }
    if (tid == 0) out[b] = red[0];
}

// ---------------- launch ------------------------------------------------------
extern "C" void kernel_launch(void* const* d_in, const int* in_sizes, int n_in,
                              void* d_out, int out_size)
{
    const float* imgA = (const float*)d_in[0];
    const float* imgB = (const float*)d_in[1];
    const float* W1   = (const float*)d_in[2];
    const float* W2   = (const float*)d_in[3];
    const float* W3   = (const float*)d_in[4];
    const float* W4   = (const float*)d_in[5];
    const float* Wr1  = (const float*)d_in[6];
    const float* Wr2  = (const float*)d_in[7];
    const float* Wd   = (const float*)d_in[8];
    const float* bd   = (const float*)d_in[9];
    float* out = (float*)d_out;

    float *featA, *featB, *corr, *r1, *r1p, *r2, *geo;
    cudaGetSymbolAddress((void**)&featA, g_featA);
    cudaGetSymbolAddress((void**)&featB, g_featB);
    cudaGetSymbolAddress((void**)&corr,  g_corr);
    cudaGetSymbolAddress((void**)&r1,    g_r1);
    cudaGetSymbolAddress((void**)&r1p,   g_r1p);
    cudaGetSymbolAddress((void**)&r2,    g_r2);
    cudaGetSymbolAddress((void**)&geo,   g_geo);

    __nv_bfloat16 *s1h,*s1m,*s1l,*s2h,*s2m,*s2l,*s3h,*s3m,*s3l;
    __nv_bfloat16 *fAh,*fAm,*fAl,*fBh,*fBm,*fBl,*ch,*cm,*cl,*wh,*wm,*wl;
    cudaGetSymbolAddress((void**)&s1h, g_s1h); cudaGetSymbolAddress((void**)&s1m, g_s1m);
    cudaGetSymbolAddress((void**)&s1l, g_s1l);
    cudaGetSymbolAddress((void**)&s2h, g_s2h); cudaGetSymbolAddress((void**)&s2m, g_s2m);
    cudaGetSymbolAddress((void**)&s2l, g_s2l);
    cudaGetSymbolAddress((void**)&s3h, g_s3h); cudaGetSymbolAddress((void**)&s3m, g_s3m);
    cudaGetSymbolAddress((void**)&s3l, g_s3l);
    cudaGetSymbolAddress((void**)&fAh, g_fAh); cudaGetSymbolAddress((void**)&fAm, g_fAm);
    cudaGetSymbolAddress((void**)&fAl, g_fAl);
    cudaGetSymbolAddress((void**)&fBh, g_fBh); cudaGetSymbolAddress((void**)&fBm, g_fBm);
    cudaGetSymbolAddress((void**)&fBl, g_fBl);
    cudaGetSymbolAddress((void**)&ch, g_ch); cudaGetSymbolAddress((void**)&cm, g_cm);
    cudaGetSymbolAddress((void**)&cl, g_cl);
    cudaGetSymbolAddress((void**)&wh, g_wh); cudaGetSymbolAddress((void**)&wm, g_wm);
    cudaGetSymbolAddress((void**)&wl, g_wl);

    // transposed+split weight regions (element offsets)
    const size_t O_W2 = 0, O_W3 = 73728, O_W4 = 368640, O_Wr1 = 1548288;
    split_w<<<(73728 + 255)/256, 256>>>(W2,  wh + O_W2,  wm + O_W2,  wl + O_W2,  64, 128, 73728);
    split_w<<<(294912 + 255)/256, 256>>>(W3, wh + O_W3,  wm + O_W3,  wl + O_W3,  128, 256, 294912);
    split_w<<<(1179648 + 255)/256, 256>>>(W4, wh + O_W4, wm + O_W4, wl + O_W4, 256, 512, 1179648);
    split_w<<<(1605632 + 255)/256, 256>>>(Wr1, wh + O_Wr1, wm + O_Wr1, wl + O_Wr1, 256, 128, 1605632);

    const int SMB = SM_U32 * 4;    // 82944 bytes dynamic smem
    auto mm2 = conv_mma<64, 128, 128, 128, 64, 64, 3, 3, 2, false, false, 0, 1, false, true, true>;
    auto mm3 = conv_mma<128, 256, 64, 64, 32, 32, 3, 3, 2, false, false, 0, 1, false, true, true>;
    auto mm4 = conv_mma<256, 512, 32, 32, 16, 16, 3, 3, 2, false, false, 0, 1, true, false, true>;
    auto mmc = conv_mma<512, 256, 16, 16, 16, 16, 1, 1, 1, false, true, 256, 1, true, true, false>;
    auto mr1 = conv_mma<256, 128, 16, 16, 10, 10, 7, 7, 1, true, false, 0, 4, true, false, false>;
    cudaFuncSetAttribute(mm2, cudaFuncAttributeMaxDynamicSharedMemorySize, SMB);
    cudaFuncSetAttribute(mm3, cudaFuncAttributeMaxDynamicSharedMemorySize, SMB);
    cudaFuncSetAttribute(mm4, cudaFuncAttributeMaxDynamicSharedMemorySize, SMB);
    cudaFuncSetAttribute(mmc, cudaFuncAttributeMaxDynamicSharedMemorySize, SMB);
    cudaFuncSetAttribute(mr1, cudaFuncAttributeMaxDynamicSharedMemorySize, SMB);

    for (int im = 0; im < 2; ++im) {
        const float* img = im ? imgB : imgA;
        float* feat = im ? featB : featA;
        __nv_bfloat16 *fh = im ? fBh : fAh, *fm = im ? fBm : fAm, *fl = im ? fBl : fAl;
        conv1_kernel<<<65536, 256>>>(img, W1, s1h, s1m, s1l);
        mm2<<<dim3(32, 2, 32), 256, SMB>>>(s1h, s1m, s1l, wh + O_W2, wm + O_W2, wl + O_W2,
                                           nullptr, s2h, s2m, s2l);
        mm3<<<dim3(8, 4, 32), 256, SMB>>>(s2h, s2m, s2l, wh + O_W3, wm + O_W3, wl + O_W3,
                                          nullptr, s3h, s3m, s3l);
        mm4<<<dim3(2, 8, 32), 256, SMB>>>(s3h, s3m, s3l, wh + O_W4, wm + O_W4, wl + O_W4,
                                          feat, nullptr, nullptr, nullptr);
        normalize_split<<<8192, 128>>>(feat, fh, fm, fl);
    }

    mmc<<<dim3(2, 4, 32), 256, SMB>>>(fAh, fAm, fAl, fBh, fBm, fBl, corr, ch, cm, cl);

    // r1 with split-K=4: grid.y = nblocks(2) * SK(4); raw partials + reduce
    mr1<<<dim3(1, 8, 32), 256, SMB>>>(ch, cm, cl, wh + O_Wr1, wm + O_Wr1, wl + O_Wr1,
                                      r1p, nullptr, nullptr, nullptr);
    reduce_r1<<<1600, 256>>>(r1p, r1);

    conv_igemm<128, 64, 10, 10, 6, 6, 5, 5, 1, true>
        <<<dim3(1, 1, 32), 256>>>(r1, Wr2, r2);

    dense_kernel<<<32, 576>>>(r2, Wd, bd, geo);
    tps_sum_kernel<<<32, 256>>>(geo, corr, out);
}